// round 1
// baseline (speedup 1.0000x reference)
#include <cuda_runtime.h>
#include <cstddef>

// O3 tensor product, MUL=64.
// out_s[w]   = sum_u a[u]*Wss[u,w] + b[u]*Wvv[u,w] + bias[w]
//   where a[u] = s1[u]*s2,  b[u] = dot(v1[u],v2)/sqrt(3)
// out_v[w,i] = (s1@Wsv)[w]*v2[i] + (v1_i@Wvs)[w]*s2
// (all reference scale factors cancel exactly: A_SCALAR/SQRT_K = 1,
//  A_VECTOR*INV_SQRT3/SQRT_K = 1)

#define MULC 64
#define THREADS 256
#define WARPS_PER_BLOCK 8
#define ROWS_PER_WARP 2

__device__ __forceinline__ float2 ldf2(const float* p) { return *(const float2*)p; }

// Shared layout (floats):
//  [0      .. 4096 )  Wss   (64x64)
//  [4096   .. 8192 )  Wvv
//  [8192   .. 12288)  Wsv
//  [12288  .. 16384)  Wvs
//  [16384  .. 16448)  bias
//  [16448  .. 24640)  staging: 8 warps * 2 rows * 64 u * 8 floats
#define SMEM_FLOATS (4 * 4096 + 64 + WARPS_PER_BLOCK * ROWS_PER_WARP * 64 * 8)

__global__ void __launch_bounds__(THREADS, 2)
o3tp_kernel(const float* __restrict__ in1,   // (n, 256)
            const float* __restrict__ in2,   // (n, 4)
            const float* __restrict__ Wss,
            const float* __restrict__ Wvv,
            const float* __restrict__ Wsv,
            const float* __restrict__ Wvs,
            const float* __restrict__ bias,
            float* __restrict__ out,          // (n, 256)
            int n)
{
    extern __shared__ float sh[];
    float* sW    = sh;                 // 4 matrices back to back
    float* sBias = sh + 4 * 4096;
    float* sStg  = sh + 4 * 4096 + 64;

    const int tid = threadIdx.x;

    // ---- load weights to shared (float4) ----
    {
        const float* srcs[4] = {Wss, Wvv, Wsv, Wvs};
#pragma unroll
        for (int m = 0; m < 4; m++) {
            const float4* src = (const float4*)srcs[m];
            float4* dst = (float4*)(sW + m * 4096);
            for (int i = tid; i < 1024; i += THREADS) dst[i] = src[i];
        }
        if (tid < 64) sBias[tid] = bias[tid];
    }
    __syncthreads();

    const float* sWss = sW;
    const float* sWvv = sW + 4096;
    const float* sWsv = sW + 8192;
    const float* sWvs = sW + 12288;

    const int warp = tid >> 5;
    const int lane = tid & 31;
    const int gwarp = blockIdx.x * WARPS_PER_BLOCK + warp;
    const int nwarps = gridDim.x * WARPS_PER_BLOCK;
    float* stage = sStg + warp * (ROWS_PER_WARP * 64 * 8);

    const float INV_SQRT3 = 0.57735026918962576451f;

    for (int row0 = gwarp * ROWS_PER_WARP; row0 < n; row0 += nwarps * ROWS_PER_WARP) {

        float s2r[ROWS_PER_WARP];
        float v2r[ROWS_PER_WARP][3];

        // ---- stage rows: per u store {a, b, s1, vx, vy, vz} ----
#pragma unroll
        for (int r = 0; r < ROWS_PER_WARP; r++) {
            const int row = row0 + r;
            const bool ok = row < n;
            const size_t b2 = (size_t)(ok ? row : 0) * 4;
            float s2  = ok ? in2[b2 + 0] : 0.0f;
            float v2x = ok ? in2[b2 + 1] : 0.0f;
            float v2y = ok ? in2[b2 + 2] : 0.0f;
            float v2z = ok ? in2[b2 + 3] : 0.0f;
            s2r[r] = s2; v2r[r][0] = v2x; v2r[r][1] = v2y; v2r[r][2] = v2z;

            const float* i1 = in1 + (size_t)(ok ? row : 0) * 256;
            float* st = stage + r * 512;
#pragma unroll
            for (int h = 0; h < 2; h++) {
                const int u = lane + 32 * h;
                float s1u = ok ? i1[u] : 0.0f;
                float vx  = ok ? i1[64 + 3 * u + 0] : 0.0f;
                float vy  = ok ? i1[64 + 3 * u + 1] : 0.0f;
                float vz  = ok ? i1[64 + 3 * u + 2] : 0.0f;
                float a = s1u * s2;
                float b = (vx * v2x + vy * v2y + vz * v2z) * INV_SQRT3;
                *(float4*)(st + u * 8)     = make_float4(a, b, s1u, vx);
                *(float2*)(st + u * 8 + 4) = make_float2(vy, vz);
            }
        }
        __syncwarp();

        // ---- accumulate: lane owns outputs w = 2*lane, 2*lane+1 ----
        float accS [ROWS_PER_WARP][2];
        float accSV[ROWS_PER_WARP][2];
        float accVS[ROWS_PER_WARP][2][3];
#pragma unroll
        for (int r = 0; r < ROWS_PER_WARP; r++) {
#pragma unroll
            for (int j = 0; j < 2; j++) {
                accS[r][j] = 0.0f; accSV[r][j] = 0.0f;
                accVS[r][j][0] = 0.0f; accVS[r][j][1] = 0.0f; accVS[r][j][2] = 0.0f;
            }
        }

        const int wcol = 2 * lane;
#pragma unroll 8
        for (int u = 0; u < 64; u++) {
            const float2 wss = ldf2(sWss + u * 64 + wcol);
            const float2 wvv = ldf2(sWvv + u * 64 + wcol);
            const float2 wsv = ldf2(sWsv + u * 64 + wcol);
            const float2 wvs = ldf2(sWvs + u * 64 + wcol);
#pragma unroll
            for (int r = 0; r < ROWS_PER_WARP; r++) {
                const float* st = stage + r * 512 + u * 8;
                const float4 t0 = *(const float4*)st;        // a, b, s1, vx
                const float2 t1 = *(const float2*)(st + 4);  // vy, vz

                accS[r][0]  = fmaf(t0.x, wss.x, accS[r][0]);
                accS[r][0]  = fmaf(t0.y, wvv.x, accS[r][0]);
                accSV[r][0] = fmaf(t0.z, wsv.x, accSV[r][0]);
                accVS[r][0][0] = fmaf(t0.w, wvs.x, accVS[r][0][0]);
                accVS[r][0][1] = fmaf(t1.x, wvs.x, accVS[r][0][1]);
                accVS[r][0][2] = fmaf(t1.y, wvs.x, accVS[r][0][2]);

                accS[r][1]  = fmaf(t0.x, wss.y, accS[r][1]);
                accS[r][1]  = fmaf(t0.y, wvv.y, accS[r][1]);
                accSV[r][1] = fmaf(t0.z, wsv.y, accSV[r][1]);
                accVS[r][1][0] = fmaf(t0.w, wvs.y, accVS[r][1][0]);
                accVS[r][1][1] = fmaf(t1.x, wvs.y, accVS[r][1][1]);
                accVS[r][1][2] = fmaf(t1.y, wvs.y, accVS[r][1][2]);
            }
        }

        // ---- epilogue + store ----
#pragma unroll
        for (int r = 0; r < ROWS_PER_WARP; r++) {
            const int row = row0 + r;
            if (row >= n) break;
            float* o = out + (size_t)row * 256;

            float2 os;
            os.x = accS[r][0] + sBias[wcol];
            os.y = accS[r][1] + sBias[wcol + 1];
            *(float2*)(o + wcol) = os;

            const float s2 = s2r[r];
            float v[6];
#pragma unroll
            for (int j = 0; j < 2; j++) {
#pragma unroll
                for (int i = 0; i < 3; i++) {
                    v[j * 3 + i] = accSV[r][j] * v2r[r][i] + accVS[r][j][i] * s2;
                }
            }
            float* ov = o + 64 + 6 * lane;
            *(float2*)(ov + 0) = make_float2(v[0], v[1]);
            *(float2*)(ov + 2) = make_float2(v[2], v[3]);
            *(float2*)(ov + 4) = make_float2(v[4], v[5]);
        }
        __syncwarp();
    }
}

extern "C" void kernel_launch(void* const* d_in, const int* in_sizes, int n_in,
                              void* d_out, int out_size)
{
    const float* in1  = (const float*)d_in[0];
    const float* in2  = (const float*)d_in[1];
    const float* Wss  = (const float*)d_in[2];
    const float* Wvv  = (const float*)d_in[3];
    const float* Wsv  = (const float*)d_in[4];
    const float* Wvs  = (const float*)d_in[5];
    const float* bias = (const float*)d_in[6];
    float* out = (float*)d_out;

    const int n = in_sizes[0] / 256;
    const int smem_bytes = SMEM_FLOATS * (int)sizeof(float);

    cudaFuncSetAttribute(o3tp_kernel, cudaFuncAttributeMaxDynamicSharedMemorySize, smem_bytes);

    const int grid = 304;  // ~2 blocks / SM (shared-mem limited), grid-stride loop
    o3tp_kernel<<<grid, THREADS, smem_bytes>>>(in1, in2, Wss, Wvv, Wsv, Wvs, bias, out, n);
}

// round 2
// speedup vs baseline: 1.0275x; 1.0275x over previous
#include <cuda_runtime.h>
#include <cstddef>

// O3 tensor product, MUL=64 (all reference scale factors cancel exactly):
//   out_s[w]   = sum_u a[u]*Wss[u,w] + b[u]*Wvv[u,w] + bias[w]
//     a[u] = s1[u]*s2 ; b[u] = dot(v1[u],v2)/sqrt(3)
//   out_v[w,i] = (s1@Wsv)[w]*v2[i] + (v1_i@Wvs)[w]*s2

#define THREADS 384
#define WARPS 12
#define RPW 4                 // rows per warp per iteration
#define STG_ROW 772           // floats per staged row: 64u*12 + 4 pad (3088B, bank-skewed)
#define SMEM_FLOATS (16384 + 64 + WARPS * RPW * STG_ROW)

typedef unsigned long long u64;

__device__ __forceinline__ u64 ff2(u64 a, u64 b, u64 c) {
    u64 d; asm("fma.rn.f32x2 %0, %1, %2, %3;" : "=l"(d) : "l"(a), "l"(b), "l"(c)); return d;
}
__device__ __forceinline__ u64 fm2(u64 a, u64 b) {
    u64 d; asm("mul.rn.f32x2 %0, %1, %2;" : "=l"(d) : "l"(a), "l"(b)); return d;
}
__device__ __forceinline__ u64 fa2(u64 a, u64 b) {
    u64 d; asm("add.rn.f32x2 %0, %1, %2;" : "=l"(d) : "l"(a), "l"(b)); return d;
}
__device__ __forceinline__ u64 dup2(float v) {
    u64 d; asm("mov.b64 %0, {%1, %1};" : "=l"(d) : "f"(v)); return d;
}
__device__ __forceinline__ float2 unp(u64 v) {
    float2 f; asm("mov.b64 {%0, %1}, %2;" : "=f"(f.x), "=f"(f.y) : "l"(v)); return f;
}

__global__ void __launch_bounds__(THREADS, 1)
o3tp_kernel(const float* __restrict__ in1,   // (n, 256)
            const float* __restrict__ in2,   // (n, 4)
            const float* __restrict__ Wss,
            const float* __restrict__ Wvv,
            const float* __restrict__ Wsv,
            const float* __restrict__ Wvs,
            const float* __restrict__ bias,
            float* __restrict__ out,          // (n, 256)
            int n)
{
    extern __shared__ float sh[];
    float* sW    = sh;            // [u][mat][col] : sW[u*256 + m*64 + col]
    float* sBias = sh + 16384;
    float* sStg  = sh + 16448;

    const int tid = threadIdx.x;

    // ---- stage weights: sW[u*256 + m*64 + col] = Wm[u*64 + col] ----
    {
        const float* srcs[4] = {Wss, Wvv, Wsv, Wvs};
#pragma unroll
        for (int m = 0; m < 4; m++) {
            const float* src = srcs[m];
            for (int idx = tid; idx < 4096; idx += THREADS) {
                int u = idx >> 6, col = idx & 63;
                sW[u * 256 + m * 64 + col] = src[idx];
            }
        }
        if (tid < 64) sBias[tid] = bias[tid];
    }
    __syncthreads();

    const int warp = tid >> 5;
    const int lane = tid & 31;
    const int sub  = lane >> 4;        // which row of the pair this lane computes
    const int cg   = lane & 15;        // column group: cols 4cg..4cg+3
    const int gwarp  = blockIdx.x * WARPS + warp;
    const int nwarps = gridDim.x * WARPS;

    float* stg = sStg + warp * (RPW * STG_ROW);
    const ulonglong2 bias2 = *(const ulonglong2*)(sBias + 4 * cg);

    const float INV_SQRT3 = 0.57735026918962576451f;

    for (int row0 = gwarp * RPW; row0 < n; row0 += nwarps * RPW) {

        // ---- stage 4 rows: per u store duplicated {aa,bb | ss,xx | yy,zz} ----
        float4 rq[RPW];
#pragma unroll
        for (int r = 0; r < RPW; r++) {
            const int row = row0 + r;
            const int rr = (row < n) ? row : 0;
            const float4 q = *(const float4*)(in2 + (size_t)rr * 4);  // s2,v2x,v2y,v2z
            rq[r] = q;
            const float* i1 = in1 + (size_t)rr * 256;
            float* st = stg + r * STG_ROW;
#pragma unroll
            for (int h = 0; h < 2; h++) {
                const int u = lane + 32 * h;
                const float s1u = i1[u];
                const float vx = i1[64 + 3 * u], vy = i1[65 + 3 * u], vz = i1[66 + 3 * u];
                const float a = s1u * q.x;
                const float b = (vx * q.y + vy * q.z + vz * q.w) * INV_SQRT3;
                float* d = st + u * 12;
                *(float4*)(d)     = make_float4(a, a, b, b);
                *(float4*)(d + 4) = make_float4(s1u, s1u, vx, vx);
                *(float4*)(d + 8) = make_float4(vy, vy, vz, vz);
            }
        }
        __syncwarp();

        // lane's two rows: pair A = row0 + sub, pair B = row0 + 2 + sub
        const float* stA = stg + (0 + sub) * STG_ROW;
        const float* stB = stg + (2 + sub) * STG_ROW;

        // acc layout: [pair][0,1]=S colpairs, [2,3]=SV, [4..9]=VS x/y/z colpairs
        u64 acc[2][10];
#pragma unroll
        for (int p = 0; p < 2; p++)
#pragma unroll
            for (int k = 0; k < 10; k++) acc[p][k] = 0ull;

#pragma unroll 4
        for (int u = 0; u < 64; u++) {
            const float* wp = sW + u * 256 + (cg << 2);
            const ulonglong2 wss = *(const ulonglong2*)(wp);
            const ulonglong2 wvv = *(const ulonglong2*)(wp + 64);
            const ulonglong2 wsv = *(const ulonglong2*)(wp + 128);
            const ulonglong2 wvs = *(const ulonglong2*)(wp + 192);
#pragma unroll
            for (int p = 0; p < 2; p++) {
                const float* st = (p == 0 ? stA : stB) + u * 12;
                const ulonglong2 ab = *(const ulonglong2*)(st);
                const ulonglong2 sx = *(const ulonglong2*)(st + 4);
                const ulonglong2 yz = *(const ulonglong2*)(st + 8);
                acc[p][0] = ff2(ab.x, wss.x, acc[p][0]);
                acc[p][1] = ff2(ab.x, wss.y, acc[p][1]);
                acc[p][0] = ff2(ab.y, wvv.x, acc[p][0]);
                acc[p][1] = ff2(ab.y, wvv.y, acc[p][1]);
                acc[p][2] = ff2(sx.x, wsv.x, acc[p][2]);
                acc[p][3] = ff2(sx.x, wsv.y, acc[p][3]);
                acc[p][4] = ff2(sx.y, wvs.x, acc[p][4]);
                acc[p][5] = ff2(sx.y, wvs.y, acc[p][5]);
                acc[p][6] = ff2(yz.x, wvs.x, acc[p][6]);
                acc[p][7] = ff2(yz.x, wvs.y, acc[p][7]);
                acc[p][8] = ff2(yz.y, wvs.x, acc[p][8]);
                acc[p][9] = ff2(yz.y, wvs.y, acc[p][9]);
            }
        }

        // ---- epilogue ----
#pragma unroll
        for (int p = 0; p < 2; p++) {
            const int ri  = p * 2 + sub;
            const int row = row0 + ri;
            if (row >= n) continue;
            const float4 q = rq[ri];
            const u64 s22 = dup2(q.x);
            const u64 vx2 = dup2(q.y);
            const u64 vy2 = dup2(q.z);
            const u64 vz2 = dup2(q.w);

            float* o = out + (size_t)row * 256;

            const float2 S0 = unp(fa2(acc[p][0], bias2.x));
            const float2 S1 = unp(fa2(acc[p][1], bias2.y));
            *(float4*)(o + 4 * cg) = make_float4(S0.x, S0.y, S1.x, S1.y);

            const float2 X0 = unp(ff2(acc[p][2], vx2, fm2(acc[p][4], s22)));
            const float2 X1 = unp(ff2(acc[p][3], vx2, fm2(acc[p][5], s22)));
            const float2 Y0 = unp(ff2(acc[p][2], vy2, fm2(acc[p][6], s22)));
            const float2 Y1 = unp(ff2(acc[p][3], vy2, fm2(acc[p][7], s22)));
            const float2 Z0 = unp(ff2(acc[p][2], vz2, fm2(acc[p][8], s22)));
            const float2 Z1 = unp(ff2(acc[p][3], vz2, fm2(acc[p][9], s22)));

            float* ov = o + 64 + 12 * cg;
            *(float4*)(ov)     = make_float4(X0.x, Y0.x, Z0.x, X0.y);
            *(float4*)(ov + 4) = make_float4(Y0.y, Z0.y, X1.x, Y1.x);
            *(float4*)(ov + 8) = make_float4(Z1.x, X1.y, Y1.y, Z1.y);
        }
        __syncwarp();
    }
}

extern "C" void kernel_launch(void* const* d_in, const int* in_sizes, int n_in,
                              void* d_out, int out_size)
{
    const float* in1  = (const float*)d_in[0];
    const float* in2  = (const float*)d_in[1];
    const float* Wss  = (const float*)d_in[2];
    const float* Wvv  = (const float*)d_in[3];
    const float* Wsv  = (const float*)d_in[4];
    const float* Wvs  = (const float*)d_in[5];
    const float* bias = (const float*)d_in[6];
    float* out = (float*)d_out;

    const int n = in_sizes[0] / 256;
    const int smem_bytes = SMEM_FLOATS * (int)sizeof(float);

    cudaFuncSetAttribute(o3tp_kernel, cudaFuncAttributeMaxDynamicSharedMemorySize, smem_bytes);

    int dev = 0, sms = 148;
    cudaGetDevice(&dev);
    cudaDeviceGetAttribute(&sms, cudaDevAttrMultiProcessorCount, dev);

    o3tp_kernel<<<sms, THREADS, smem_bytes>>>(in1, in2, Wss, Wvv, Wsv, Wvs, bias, out, n);
}

// round 4
// speedup vs baseline: 2.3242x; 2.2621x over previous
#include <cuda_runtime.h>
#include <cuda_bf16.h>
#include <cstdint>
#include <cstddef>

// O3 tensor product, MUL=64, via mma.sync bf16 (hi/lo split, fp32 accum).
//   Q1 = s1 @ Wss ; Q2 = b @ Wvv ; P3 = s1 @ Wsv ; P4i = v1_i @ Wvs
//   out_s       = s2*Q1 + Q2 + bias
//   out_v[w][i] = P3[w]*v2_i + P4i[w]*s2
// (all reference scale factors cancel; b = dot(v1,v2)/sqrt(3))

#define THREADS 256
#define RPC 32                      // rows per chunk
#define MAT_BYTES (RPC * 128)       // one staged A matrix: 32 rows x 128B (64 bf16)
#define BUF_BYTES (10 * MAT_BYTES + 512)
#define SMEM_BYTES (2 * BUF_BYTES)

typedef unsigned int u32;

// 16B-block XOR swizzle offset for staged A: row r, 8-elem group ug
__device__ __forceinline__ u32 sw_off(int r, int ug) {
    return (u32)(r * 128 + ((ug ^ (r & 7)) << 4));
}

__device__ __forceinline__ u32 smem_u32(const void* p) {
    u32 a; asm("{ .reg .u64 t; cvta.to.shared.u64 t, %1; cvt.u32.u64 %0, t; }" : "=r"(a) : "l"(p));
    return a;
}

__device__ __forceinline__ void ldsm4(u32* d, u32 addr) {
    asm volatile("ldmatrix.sync.aligned.m8n8.x4.shared.b16 {%0,%1,%2,%3}, [%4];"
                 : "=r"(d[0]), "=r"(d[1]), "=r"(d[2]), "=r"(d[3]) : "r"(addr));
}

__device__ __forceinline__ void mma16816(float* c, const u32* a, const u32* b) {
    asm volatile("mma.sync.aligned.m16n8k16.row.col.f32.bf16.bf16.f32 "
                 "{%0,%1,%2,%3},{%4,%5,%6,%7},{%8,%9},{%0,%1,%2,%3};"
                 : "+f"(c[0]), "+f"(c[1]), "+f"(c[2]), "+f"(c[3])
                 : "r"(a[0]), "r"(a[1]), "r"(a[2]), "r"(a[3]), "r"(b[0]), "r"(b[1]));
}

// split two floats into packed bf16x2 hi and lo (lo = residual)
__device__ __forceinline__ void split2(float x0, float x1, u32& hi, u32& lo) {
    __nv_bfloat162 h = __floats2bfloat162_rn(x0, x1);
    float r0 = x0 - __bfloat162float(h.x);
    float r1 = x1 - __bfloat162float(h.y);
    __nv_bfloat162 l = __floats2bfloat162_rn(r0, r1);
    hi = *(u32*)&h; lo = *(u32*)&l;
}

// pack 8 floats -> hi uint4 + lo uint4 (bf16)
__device__ __forceinline__ void pack8(const float* x, uint4& hi, uint4& lo) {
    u32 h0,h1,h2,h3,l0,l1,l2,l3;
    split2(x[0], x[1], h0, l0);
    split2(x[2], x[3], h1, l1);
    split2(x[4], x[5], h2, l2);
    split2(x[6], x[7], h3, l3);
    hi = make_uint4(h0, h1, h2, h3);
    lo = make_uint4(l0, l1, l2, l3);
}

// A-matrix order in staging: 0 s1h 1 s1l 2 bh 3 bl 4 xh 5 xl 6 yh 7 yl 8 zh 9 zl
__device__ __forceinline__ void build_chunk(char* buf, const float* __restrict__ in1,
                                            const float* __restrict__ in2,
                                            int row0, int n, int t)
{
    const int r = t >> 3, ug = t & 7;
    int row = row0 + r; if (row >= n) row = n - 1;
    const float4* p1 = (const float4*)(in1 + (size_t)row * 256);

    const float4 q = *(const float4*)(in2 + (size_t)row * 4);   // s2, v2x, v2y, v2z
    if (ug == 0) *(float4*)(buf + 10 * MAT_BYTES + r * 16) = q;

    const float4 s1a = p1[2 * ug], s1b = p1[2 * ug + 1];
    float4 v[6];
#pragma unroll
    for (int i = 0; i < 6; i++) v[i] = p1[16 + 6 * ug + i];
    const float* vv = (const float*)v;            // 24 floats: v1[u][xyz], u = 8ug..8ug+7

    const float s1[8] = { s1a.x, s1a.y, s1a.z, s1a.w, s1b.x, s1b.y, s1b.z, s1b.w };
    const float INV_SQRT3 = 0.57735026918962576451f;
    float bb[8], vx[8], vy[8], vz[8];
#pragma unroll
    for (int j = 0; j < 8; j++) {
        vx[j] = vv[3 * j]; vy[j] = vv[3 * j + 1]; vz[j] = vv[3 * j + 2];
        bb[j] = (vx[j] * q.y + vy[j] * q.z + vz[j] * q.w) * INV_SQRT3;
    }

    const u32 off = sw_off(r, ug);
    uint4 hi, lo;
    pack8(s1, hi, lo);
    *(uint4*)(buf + 0 * MAT_BYTES + off) = hi; *(uint4*)(buf + 1 * MAT_BYTES + off) = lo;
    pack8(bb, hi, lo);
    *(uint4*)(buf + 2 * MAT_BYTES + off) = hi; *(uint4*)(buf + 3 * MAT_BYTES + off) = lo;
    pack8(vx, hi, lo);
    *(uint4*)(buf + 4 * MAT_BYTES + off) = hi; *(uint4*)(buf + 5 * MAT_BYTES + off) = lo;
    pack8(vy, hi, lo);
    *(uint4*)(buf + 6 * MAT_BYTES + off) = hi; *(uint4*)(buf + 7 * MAT_BYTES + off) = lo;
    pack8(vz, hi, lo);
    *(uint4*)(buf + 8 * MAT_BYTES + off) = hi; *(uint4*)(buf + 9 * MAT_BYTES + off) = lo;
}

__global__ void __launch_bounds__(THREADS, 1)
o3tp_mma_kernel(const float* __restrict__ in1, const float* __restrict__ in2,
                const float* __restrict__ Wss, const float* __restrict__ Wvv,
                const float* __restrict__ Wsv, const float* __restrict__ Wvs,
                const float* __restrict__ bias, float* __restrict__ out, int n)
{
    extern __shared__ char smem[];
    const u32 sbase = smem_u32(smem);
    const int t = threadIdx.x, wid = t >> 5, lane = t & 31;

    // ---- persistent B fragments: warp's n-slice (8 cols) of all 4 matrices ----
    u32 Bh[4][4][2], Bl[4][4][2];
    {
        const int wcol = wid * 8 + (lane >> 2);
        const float* Ws[4] = { Wss, Wvv, Wsv, Wvs };
#pragma unroll
        for (int m = 0; m < 4; m++)
#pragma unroll
            for (int kt = 0; kt < 4; kt++)
#pragma unroll
                for (int b2 = 0; b2 < 2; b2++) {
                    const int u = kt * 16 + (lane & 3) * 2 + b2 * 8;
                    const float w0 = __ldg(Ws[m] + u * 64 + wcol);
                    const float w1 = __ldg(Ws[m] + (u + 1) * 64 + wcol);
                    split2(w0, w1, Bh[m][kt][b2], Bl[m][kt][b2]);
                }
    }
    float2 bias2;
    {
        const int w0 = wid * 8 + (lane & 3) * 2;
        bias2 = make_float2(__ldg(bias + w0), __ldg(bias + w0 + 1));
    }

    const int nch = (n + RPC - 1) / RPC;
    int c = blockIdx.x;
    if (c < nch) build_chunk(smem, in1, in2, c * RPC, n, t);
    __syncthreads();

    int p = 0;
    for (; c < nch; c += gridDim.x) {
        const int cn = c + gridDim.x;
        if (cn < nch) build_chunk(smem + (p ^ 1) * BUF_BYTES, in1, in2, cn * RPC, n, t);

        // ---- MMA phase on buffer p ----
        float acc[6][2][4];
#pragma unroll
        for (int g = 0; g < 6; g++)
#pragma unroll
            for (int mt = 0; mt < 2; mt++)
#pragma unroll
                for (int k = 0; k < 4; k++) acc[g][mt][k] = 0.0f;

        const u32 abase = sbase + (u32)(p * BUF_BYTES);
        const int rl = (lane & 15);
        const int rlo = rl & 7;
#pragma unroll
        for (int kt = 0; kt < 4; kt++) {
#pragma unroll
            for (int mt = 0; mt < 2; mt++) {
                const int rr = mt * 16 + rl;
                const int cb = (kt * 2 + (lane >> 4)) ^ rlo;
                const u32 aoff = abase + (u32)(rr * 128 + cb * 16);
                u32 ah[4], al[4];
                // s1 -> Wss (acc0) and Wsv (acc2)
                ldsm4(ah, aoff + 0 * MAT_BYTES);
                ldsm4(al, aoff + 1 * MAT_BYTES);
                mma16816(acc[0][mt], ah, Bh[0][kt]);
                mma16816(acc[0][mt], al, Bh[0][kt]);
                mma16816(acc[0][mt], ah, Bl[0][kt]);
                mma16816(acc[2][mt], ah, Bh[2][kt]);
                mma16816(acc[2][mt], al, Bh[2][kt]);
                mma16816(acc[2][mt], ah, Bl[2][kt]);
                // b -> Wvv (acc1)
                ldsm4(ah, aoff + 2 * MAT_BYTES);
                ldsm4(al, aoff + 3 * MAT_BYTES);
                mma16816(acc[1][mt], ah, Bh[1][kt]);
                mma16816(acc[1][mt], al, Bh[1][kt]);
                mma16816(acc[1][mt], ah, Bl[1][kt]);
                // vx,vy,vz -> Wvs (acc3..5)
#pragma unroll
                for (int i = 0; i < 3; i++) {
                    ldsm4(ah, aoff + (4 + 2 * i) * MAT_BYTES);
                    ldsm4(al, aoff + (5 + 2 * i) * MAT_BYTES);
                    mma16816(acc[3 + i][mt], ah, Bh[3][kt]);
                    mma16816(acc[3 + i][mt], al, Bh[3][kt]);
                    mma16816(acc[3 + i][mt], ah, Bl[3][kt]);
                }
            }
        }

        // ---- epilogue ----
        const float4* sin2 = (const float4*)(smem + p * BUF_BYTES + 10 * MAT_BYTES);
        const int row0 = c * RPC;
        const int wc = wid * 8 + (lane & 3) * 2;
#pragma unroll
        for (int mt = 0; mt < 2; mt++) {
#pragma unroll
            for (int h = 0; h < 2; h++) {
                const int rloc = (lane >> 2) + h * 8 + mt * 16;
                const int row = row0 + rloc;
                if (row >= n) continue;
                const float4 q = sin2[rloc];
                float* o = out + (size_t)row * 256;
                const int ci = h * 2;
                const float s0 = q.x * acc[0][mt][ci]     + acc[1][mt][ci]     + bias2.x;
                const float s1v = q.x * acc[0][mt][ci + 1] + acc[1][mt][ci + 1] + bias2.y;
                *(float2*)(o + wc) = make_float2(s0, s1v);

                float vv6[6];
#pragma unroll
                for (int j = 0; j < 2; j++) {
                    const float p3 = acc[2][mt][ci + j];
                    vv6[3 * j]     = p3 * q.y + acc[3][mt][ci + j] * q.x;
                    vv6[3 * j + 1] = p3 * q.z + acc[4][mt][ci + j] * q.x;
                    vv6[3 * j + 2] = p3 * q.w + acc[5][mt][ci + j] * q.x;
                }
                float* ov = o + 64 + 3 * wc;
                *(float2*)(ov)     = make_float2(vv6[0], vv6[1]);
                *(float2*)(ov + 2) = make_float2(vv6[2], vv6[3]);
                *(float2*)(ov + 4) = make_float2(vv6[4], vv6[5]);
            }
        }
        __syncthreads();
        p ^= 1;
    }
}

extern "C" void kernel_launch(void* const* d_in, const int* in_sizes, int n_in,
                              void* d_out, int out_size)
{
    const float* in1  = (const float*)d_in[0];
    const float* in2  = (const float*)d_in[1];
    const float* Wss  = (const float*)d_in[2];
    const float* Wvv  = (const float*)d_in[3];
    const float* Wsv  = (const float*)d_in[4];
    const float* Wvs  = (const float*)d_in[5];
    const float* bias = (const float*)d_in[6];
    float* out = (float*)d_out;

    const int n = in_sizes[0] / 256;

    cudaFuncSetAttribute(o3tp_mma_kernel, cudaFuncAttributeMaxDynamicSharedMemorySize, SMEM_BYTES);

    int dev = 0, sms = 148;
    cudaGetDevice(&dev);
    cudaDeviceGetAttribute(&sms, cudaDevAttrMultiProcessorCount, dev);

    o3tp_mma_kernel<<<2 * sms, THREADS, SMEM_BYTES>>>(in1, in2, Wss, Wvv, Wsv, Wvs, bias, out, n);
}